// round 5
// baseline (speedup 1.0000x reference)
#include <cuda_runtime.h>
#include <math.h>
#include <stdint.h>

// ---------------------------------------------------------------------------
// BDH block: B=2, T=2048, D=512, NH=8, N=256, 3 layers.
// GEMMs on tf32 tensor cores (mma.sync m16n8k8), fp32 accumulate.
// Fragment-packed smem layout: per-kk operand fetch = LDS.128/LDS.64.
// ---------------------------------------------------------------------------

constexpr int Bb = 2, Tt = 2048, Dd = 512, NHh = 8, Nn = 256;
constexpr int BT = Bb * Tt;        // 4096
constexpr int BH = Bb * NHh;       // 16
constexpr int HN = NHh * Nn;       // 2048
constexpr float LN_EPS = 1e-5f;
constexpr float TWO_PI = 6.283185307179586f;

#define BMT 128
#define BNT 128
#define BKT 32

// Scratch (device globals: no allocation allowed)
__device__ float g_xs   [(size_t)Bb * Tt * Dd];
__device__ float g_tmp  [(size_t)Bb * Tt * Dd];
__device__ float g_xsp  [(size_t)BH * Tt * Nn];
__device__ float g_qr   [(size_t)BH * Tt * Nn];
__device__ float g_ykv  [(size_t)BH * Tt * Dd];
__device__ float g_xy   [(size_t)Bb * Tt * NHh * Nn];
__device__ float g_scores[(size_t)BH * Tt * Tt];

__device__ __forceinline__ uint32_t f2tf(float f)
{
    uint32_t u;
    asm("cvt.rna.tf32.f32 %0, %1;" : "=r"(u) : "f"(f));
    return u;
}

// ---------------------------------------------------------------------------
// 128x128 tf32 MMA tile, fragment-packed smem.
// 256 threads = 8 warps in 2(m) x 4(n); warp tile 64x32 = 4x4 m16n8k8 frags.
//
// A element (m in 0..127, k in 0..31) lives at
//   As_p[m>>6][(m>>4)&3][k>>3][(m&7)*4 + (k&3)][((m>>3)&1) + 2*((k>>2)&1)]
// so thread `lane` of warp-m `wm` fetches frag (mi,kg) with ONE LDS.128.
// B element (k in 0..31, n in 0..127) lives at
//   Bs_p[n>>5][(n>>3)&3][k>>3][(n&7)*4 + (k&3)][(k>>2)&1]
// fetched per (nj,kg) with ONE LDS.64.
//
// acc[mi][nj][e]: e -> {(r,c),(r,c+1),(r+8,c),(r+8,c+1)},
//   r = lane>>2, c = (lane&3)*2 inside fragment (mi*16, nj*8).
// ---------------------------------------------------------------------------
template <bool BNK>
__device__ __forceinline__ void mma_tile128(
    const float* __restrict__ A, int lda,
    const float* __restrict__ Bm, int ldb,
    int kCount, float acc[4][4][4])
{
    __shared__ __align__(16) uint32_t As_p[2][4][4][32][4];   // 16KB
    __shared__ __align__(16) uint32_t Bs_p[4][4][4][32][2];   // 16KB
    const int tid = threadIdx.x;
    const int lane = tid & 31, warp = tid >> 5;
    const int wm = warp >> 2;              // warp m group (0..1)
    const int wn = warp & 3;               // warp n group (0..3)

    for (int k0 = 0; k0 < kCount; k0 += BKT) {
        // ---- A: 128 x 32 into packed layout ----
        #pragma unroll
        for (int l = 0; l < 4; l++) {
            int idx = tid + l * 256;
            int m = idx >> 3, seg = (idx & 7) << 2;   // 4 consecutive k
            float4 v = *(const float4*)(A + (size_t)m * lda + k0 + seg);
            int awm = m >> 6, mi = (m >> 4) & 3, ar = m & 7, ph = (m >> 3) & 1;
            int kg = seg >> 3, ch = (seg >> 2) & 1;
            int e = ph + 2 * ch;
            uint32_t* p = &As_p[awm][mi][kg][ar * 4][e];
            p[0]  = f2tf(v.x);
            p[4]  = f2tf(v.y);
            p[8]  = f2tf(v.z);
            p[12] = f2tf(v.w);
        }
        // ---- B ----
        if (BNK) {
            // B stored [n][k]: float4 = 4 consecutive k, fixed n
            #pragma unroll
            for (int l = 0; l < 4; l++) {
                int idx = tid + l * 256;
                int n = idx >> 3, seg = (idx & 7) << 2;
                float4 v = *(const float4*)(Bm + (size_t)n * ldb + k0 + seg);
                int bwn = n >> 5, nj = (n >> 3) & 3, ar = n & 7;
                int kg = seg >> 3, ch = (seg >> 2) & 1;
                uint32_t* p = &Bs_p[bwn][nj][kg][ar * 4][ch];
                p[0] = f2tf(v.x);
                p[2] = f2tf(v.y);
                p[4] = f2tf(v.z);
                p[6] = f2tf(v.w);
            }
        } else {
            // B stored [k][n]: float4 = 4 consecutive n, fixed k
            #pragma unroll
            for (int l = 0; l < 4; l++) {
                int idx = tid + l * 256;
                int k = idx >> 5, nseg = (idx & 31) << 2;
                float4 v = *(const float4*)(Bm + (size_t)(k0 + k) * ldb + nseg);
                int kg = k >> 3, ac = k & 3, ch = (k >> 2) & 1;
                int bwn = nseg >> 5, nj = (nseg >> 3) & 3, ar0 = nseg & 7;
                uint32_t* p = &Bs_p[bwn][nj][kg][ar0 * 4 + ac][ch];
                p[8]  = f2tf(v.y);   // ar0+1
                p[0]  = f2tf(v.x);   // ar0
                p[16] = f2tf(v.z);   // ar0+2
                p[24] = f2tf(v.w);   // ar0+3
            }
        }
        __syncthreads();

        #pragma unroll
        for (int kg = 0; kg < 4; kg++) {
            uint4 a[4];
            uint2 b[4];
            #pragma unroll
            for (int mi = 0; mi < 4; mi++)
                a[mi] = *(const uint4*)&As_p[wm][mi][kg][lane][0];
            #pragma unroll
            for (int nj = 0; nj < 4; nj++)
                b[nj] = *(const uint2*)&Bs_p[wn][nj][kg][lane][0];
            #pragma unroll
            for (int mi = 0; mi < 4; mi++)
                #pragma unroll
                for (int nj = 0; nj < 4; nj++)
                    asm volatile(
                        "mma.sync.aligned.m16n8k8.row.col.f32.tf32.tf32.f32 "
                        "{%0,%1,%2,%3}, {%4,%5,%6,%7}, {%8,%9}, {%0,%1,%2,%3};"
                        : "+f"(acc[mi][nj][0]), "+f"(acc[mi][nj][1]),
                          "+f"(acc[mi][nj][2]), "+f"(acc[mi][nj][3])
                        : "r"(a[mi].x), "r"(a[mi].y), "r"(a[mi].z), "r"(a[mi].w),
                          "r"(b[nj].x), "r"(b[nj].y));
        }
        __syncthreads();
    }
}

// Epilogue index helpers
#define EPI_SETUP \
    const int lane = threadIdx.x & 31, warp = threadIdx.x >> 5; \
    const int am = (warp >> 2) * 64, bn = (warp & 3) * 32; \
    const int er = lane >> 2, ec = (lane & 3) * 2;

// ---------------------------------------------------------------------------
// LN helpers
// ---------------------------------------------------------------------------
__device__ __forceinline__ void block_sum2(float& s, float& q)
{
    __shared__ float shs[8], shq[8];
    __syncthreads();
    #pragma unroll
    for (int o = 16; o > 0; o >>= 1) {
        s += __shfl_xor_sync(0xffffffffu, s, o);
        q += __shfl_xor_sync(0xffffffffu, q, o);
    }
    int w = threadIdx.x >> 5;
    if ((threadIdx.x & 31) == 0) { shs[w] = s; shq[w] = q; }
    __syncthreads();
    s = 0.f; q = 0.f;
    #pragma unroll
    for (int i = 0; i < 8; i++) { s += shs[i]; q += shq[i]; }
}

__device__ __forceinline__ void ln512_pair(float v0, float v1, float& o0, float& o1)
{
    float s = v0 + v1, q = v0 * v0 + v1 * v1;
    block_sum2(s, q);
    float mu  = s * (1.f / 512.f);
    float var = q * (1.f / 512.f) - mu * mu;
    float r   = rsqrtf(var + LN_EPS);
    o0 = (v0 - mu) * r;
    o1 = (v1 - mu) * r;
}

// ---------------------------------------------------------------------------
// Kernels
// ---------------------------------------------------------------------------

__global__ __launch_bounds__(256, 2) void k_inproj(
    const float* __restrict__ x, const float* __restrict__ w, const float* __restrict__ bias)
{
    int n0 = blockIdx.x * BNT, m0 = blockIdx.y * BMT;
    float acc[4][4][4] = {};
    mma_tile128<false>(x + (size_t)m0 * Dd, Dd, w + n0, Dd, Dd, acc);
    EPI_SETUP;
    #pragma unroll
    for (int mi = 0; mi < 4; mi++)
        #pragma unroll
        for (int nj = 0; nj < 4; nj++) {
            int m = m0 + am + mi * 16 + er;
            int n = n0 + bn + nj * 8 + ec;
            g_tmp[(size_t)m * Dd + n]           = acc[mi][nj][0] + bias[n];
            g_tmp[(size_t)m * Dd + n + 1]       = acc[mi][nj][1] + bias[n + 1];
            g_tmp[(size_t)(m + 8) * Dd + n]     = acc[mi][nj][2] + bias[n];
            g_tmp[(size_t)(m + 8) * Dd + n + 1] = acc[mi][nj][3] + bias[n + 1];
        }
}

__global__ __launch_bounds__(256) void k_ln_inproj()
{
    size_t row = blockIdx.x;
    const float* p = g_tmp + row * 512;
    int t = threadIdx.x;
    float o0, o1;
    ln512_pair(p[t], p[t + 256], o0, o1);
    g_xs[row * 512 + t] = o0;
    g_xs[row * 512 + t + 256] = o1;
}

// encode + relu + rope. ec is always even -> each (e0,e1)/(e2,e3) is a rope pair.
__global__ __launch_bounds__(256, 2) void k_enc_rope(const float* __restrict__ enc)
{
    int z = blockIdx.z;
    int b = z / NHh, h = z % NHh;
    int n0 = blockIdx.x * BNT, m0 = blockIdx.y * BMT;
    const float* A  = g_xs + (size_t)b * Tt * Dd + (size_t)m0 * Dd;
    const float* Bm = enc + (size_t)h * Dd * Nn + n0;
    float acc[4][4][4] = {};
    mma_tile128<false>(A, Dd, Bm, Nn, Dd, acc);
    EPI_SETUP;
    #pragma unroll
    for (int mi = 0; mi < 4; mi++)
        #pragma unroll
        for (int nj = 0; nj < 4; nj++) {
            int ne = n0 + bn + nj * 8 + ec;   // even column (rope pair start)
            float freq = exp2f((float)ne * (-1.f / 16.f)) * (1.f / TWO_PI);
            #pragma unroll
            for (int hh = 0; hh < 2; hh++) {
                int t = m0 + am + mi * 16 + er + hh * 8;
                float v0 = fmaxf(acc[mi][nj][hh * 2], 0.f);
                float v1 = fmaxf(acc[mi][nj][hh * 2 + 1], 0.f);
                float ph = (float)t * freq;
                ph = (ph - floorf(ph)) * TWO_PI;
                float sp, cp;
                sincosf(ph, &sp, &cp);
                size_t base = ((size_t)z * Tt + t) * Nn + ne;
                g_xsp[base]     = v0;
                g_xsp[base + 1] = v1;
                g_qr[base]      = v0 * cp - v1 * sp;
                g_qr[base + 1]  = v1 * cp + v0 * sp;
            }
        }
}

// scores = QR @ QR^T, strict-lower causal
__global__ __launch_bounds__(256, 2) void k_qk()
{
    int stile = blockIdx.x, ttile = blockIdx.y, z = blockIdx.z;
    if (stile > ttile) return;
    const float* Q  = g_qr + ((size_t)z * Tt + (size_t)ttile * BMT) * Nn;
    const float* Kp = g_qr + ((size_t)z * Tt + (size_t)stile * BNT) * Nn;
    float acc[4][4][4] = {};
    mma_tile128<true>(Q, Nn, Kp, Nn, Nn, acc);
    EPI_SETUP;
    #pragma unroll
    for (int mi = 0; mi < 4; mi++)
        #pragma unroll
        for (int nj = 0; nj < 4; nj++) {
            int t = ttile * BMT + am + mi * 16 + er;
            int s = stile * BNT + bn + nj * 8 + ec;
            size_t r0 = ((size_t)z * Tt + t) * Tt;
            size_t r1 = ((size_t)z * Tt + t + 8) * Tt;
            g_scores[r0 + s]     = (t > s)     ? acc[mi][nj][0] : 0.f;
            g_scores[r0 + s + 1] = (t > s + 1) ? acc[mi][nj][1] : 0.f;
            g_scores[r1 + s]     = (t + 8 > s)     ? acc[mi][nj][2] : 0.f;
            g_scores[r1 + s + 1] = (t + 8 > s + 1) ? acc[mi][nj][3] : 0.f;
        }
}

// yKV = scores @ xs (causal K-extent)
__global__ __launch_bounds__(256, 2) void k_sv()
{
    int dtile = blockIdx.x, ttile = blockIdx.y, z = blockIdx.z;
    int b = z / NHh;
    const float* A  = g_scores + ((size_t)z * Tt + (size_t)ttile * BMT) * Tt;
    const float* Bm = g_xs + (size_t)b * Tt * Dd + dtile * BNT;
    float acc[4][4][4] = {};
    mma_tile128<false>(A, Tt, Bm, Dd, (ttile + 1) * BMT, acc);
    EPI_SETUP;
    #pragma unroll
    for (int mi = 0; mi < 4; mi++)
        #pragma unroll
        for (int nj = 0; nj < 4; nj++) {
            int t = ttile * BMT + am + mi * 16 + er;
            int d = dtile * BNT + bn + nj * 8 + ec;
            size_t r0 = ((size_t)z * Tt + t) * Dd;
            size_t r1 = ((size_t)z * Tt + t + 8) * Dd;
            g_ykv[r0 + d]     = acc[mi][nj][0];
            g_ykv[r0 + d + 1] = acc[mi][nj][1];
            g_ykv[r1 + d]     = acc[mi][nj][2];
            g_ykv[r1 + d + 1] = acc[mi][nj][3];
        }
}

__global__ __launch_bounds__(256) void k_ln_ykv()
{
    size_t row = blockIdx.x;
    float* p = g_ykv + row * 512;
    int t = threadIdx.x;
    float o0, o1;
    ln512_pair(p[t], p[t + 256], o0, o1);
    p[t] = o0;
    p[t + 256] = o1;
}

// y_sparse = relu(ln(yKV) @ encv[h]); xy = x_sparse * y_sparse -> [b,t,h,n]
__global__ __launch_bounds__(256, 2) void k_venc_mul(const float* __restrict__ encv)
{
    int z = blockIdx.z;
    int b = z / NHh, h = z % NHh;
    int n0 = blockIdx.x * BNT, m0 = blockIdx.y * BMT;
    const float* A  = g_ykv + (size_t)z * Tt * Dd + (size_t)m0 * Dd;
    const float* Bm = encv + (size_t)h * Dd * Nn + n0;
    float acc[4][4][4] = {};
    mma_tile128<false>(A, Dd, Bm, Nn, Dd, acc);
    EPI_SETUP;
    #pragma unroll
    for (int mi = 0; mi < 4; mi++)
        #pragma unroll
        for (int nj = 0; nj < 4; nj++) {
            int n = n0 + bn + nj * 8 + ec;
            #pragma unroll
            for (int hh = 0; hh < 2; hh++) {
                int t = m0 + am + mi * 16 + er + hh * 8;
                size_t src = ((size_t)z * Tt + t) * Nn + n;
                size_t dst = (((size_t)(b * Tt + t)) * NHh + h) * Nn + n;
                float y0 = fmaxf(acc[mi][nj][hh * 2], 0.f);
                float y1 = fmaxf(acc[mi][nj][hh * 2 + 1], 0.f);
                g_xy[dst]     = y0 * g_xsp[src];
                g_xy[dst + 1] = y1 * g_xsp[src + 1];
            }
        }
}

// yMLP = xy[4096,2048] @ decoder[2048,512] -> g_tmp
__global__ __launch_bounds__(256, 2) void k_dec(const float* __restrict__ decw)
{
    int n0 = blockIdx.x * BNT, m0 = blockIdx.y * BMT;
    float acc[4][4][4] = {};
    mma_tile128<false>(g_xy + (size_t)m0 * HN, HN, decw + n0, Dd, HN, acc);
    EPI_SETUP;
    #pragma unroll
    for (int mi = 0; mi < 4; mi++)
        #pragma unroll
        for (int nj = 0; nj < 4; nj++) {
            int m = m0 + am + mi * 16 + er;
            int n = n0 + bn + nj * 8 + ec;
            g_tmp[(size_t)m * Dd + n]           = acc[mi][nj][0];
            g_tmp[(size_t)m * Dd + n + 1]       = acc[mi][nj][1];
            g_tmp[(size_t)(m + 8) * Dd + n]     = acc[mi][nj][2];
            g_tmp[(size_t)(m + 8) * Dd + n + 1] = acc[mi][nj][3];
        }
}

__global__ __launch_bounds__(256) void k_resid_ln()
{
    size_t row = blockIdx.x;
    const float* a = g_xs + row * 512;
    const float* bp = g_tmp + row * 512;
    int t = threadIdx.x;
    float l0, l1;
    ln512_pair(bp[t], bp[t + 256], l0, l1);
    float t0 = a[t] + l0, t1 = a[t + 256] + l1;
    float o0, o1;
    ln512_pair(t0, t1, o0, o1);
    g_xs[row * 512 + t] = o0;
    g_xs[row * 512 + t + 256] = o1;
}

__global__ __launch_bounds__(256, 2) void k_head(
    const float* __restrict__ hw, const float* __restrict__ hb, float* __restrict__ out)
{
    int n0 = blockIdx.x * BNT, m0 = blockIdx.y * BMT;
    float acc[4][4][4] = {};
    mma_tile128<false>(g_xs + (size_t)m0 * Dd, Dd, hw + n0, Dd, Dd, acc);
    EPI_SETUP;
    #pragma unroll
    for (int mi = 0; mi < 4; mi++)
        #pragma unroll
        for (int nj = 0; nj < 4; nj++) {
            int m = m0 + am + mi * 16 + er;
            int n = n0 + bn + nj * 8 + ec;
            out[(size_t)m * Dd + n]           = acc[mi][nj][0] + hb[n];
            out[(size_t)m * Dd + n + 1]       = acc[mi][nj][1] + hb[n + 1];
            out[(size_t)(m + 8) * Dd + n]     = acc[mi][nj][2] + hb[n];
            out[(size_t)(m + 8) * Dd + n + 1] = acc[mi][nj][3] + hb[n + 1];
        }
}

// ---------------------------------------------------------------------------
extern "C" void kernel_launch(void* const* d_in, const int* in_sizes, int n_in,
                              void* d_out, int out_size)
{
    const float* x    = (const float*)d_in[0];
    const float* w_in = (const float*)d_in[1];
    const float* b_in = (const float*)d_in[2];
    const float* enc  = (const float*)d_in[3];
    const float* encv = (const float*)d_in[4];
    const float* dec  = (const float*)d_in[5];
    const float* hw   = (const float*)d_in[6];
    const float* hb   = (const float*)d_in[7];
    float* out = (float*)d_out;

    dim3 blk(256);

    k_inproj<<<dim3(Dd / BNT, BT / BMT), blk>>>(x, w_in, b_in);
    k_ln_inproj<<<BT, 256>>>();

    for (int layer = 0; layer < 3; layer++) {
        k_enc_rope<<<dim3(Nn / BNT, Tt / BMT, BH), blk>>>(enc);
        k_qk<<<dim3(Tt / BNT, Tt / BMT, BH), blk>>>();
        k_sv<<<dim3(Dd / BNT, Tt / BMT, BH), blk>>>();
        k_ln_ykv<<<BH * Tt, 256>>>();
        k_venc_mul<<<dim3(Nn / BNT, Tt / BMT, BH), blk>>>(encv);
        k_dec<<<dim3(Dd / BNT, BT / BMT), blk>>>(dec);
        k_resid_ln<<<BT, 256>>>();
    }

    k_head<<<dim3(Dd / BNT, BT / BMT), blk>>>(hw, hb, out);
}

// round 6
// speedup vs baseline: 2.9348x; 2.9348x over previous
#include <cuda_runtime.h>
#include <math.h>
#include <stdint.h>

// ---------------------------------------------------------------------------
// BDH block: B=2, T=2048, D=512, NH=8, N=256, 3 layers.
// tf32 mma.sync m16n8k8, fp32 accumulate.
// cp.async double-buffered tiles; all GEMM inputs pre-rounded to tf32 bits.
// ---------------------------------------------------------------------------

constexpr int Bb = 2, Tt = 2048, Dd = 512, NHh = 8, Nn = 256;
constexpr int BT = Bb * Tt;        // 4096
constexpr int BH = Bb * NHh;       // 16
constexpr int HN = NHh * Nn;       // 2048
constexpr float LN_EPS = 1e-5f;
constexpr float TWO_PI = 6.283185307179586f;

#define BMT 128
#define BNT 128
#define BKT 32

constexpr int A_STRIDE = 36;                 // floats per A row (pad: 4*ar+ac distinct mod 32)
constexpr int B_STRIDE_KN = 136;             // floats per B[k][n] row (8*ac+ar distinct)
constexpr int STAGE_F = 128 * 36;            // 4608 floats per stage (A; also >= 32*136=4352 for B)
constexpr int SMEM_BYTES = 4 * STAGE_F * 4;  // 2 stages A + 2 stages B = 73728 B

// Scratch (device globals: no allocation allowed)
__device__ float g_xs   [(size_t)Bb * Tt * Dd];           // full-precision residual stream
__device__ float g_xs_r [(size_t)Bb * Tt * Dd];           // tf32-rounded copy for GEMMs
__device__ float g_tmp  [(size_t)Bb * Tt * Dd];
__device__ float g_xsp  [(size_t)BH * Tt * Nn];           // full precision (gating only)
__device__ float g_qr   [(size_t)BH * Tt * Nn];           // rounded at write
__device__ float g_ykv  [(size_t)BH * Tt * Dd];           // LN writes rounded
__device__ float g_xy   [(size_t)Bb * Tt * NHh * Nn];     // rounded at write
__device__ float g_scores[(size_t)BH * Tt * Tt];          // rounded at write
// Pre-rounded inputs
__device__ float g_x_r  [(size_t)Bb * Tt * Dd];
__device__ float g_win_r[(size_t)Dd * Dd];
__device__ float g_enc_r[(size_t)NHh * Dd * Nn];
__device__ float g_encv_r[(size_t)NHh * Dd * Nn];
__device__ float g_dec_r[(size_t)HN * Dd];
__device__ float g_hw_r [(size_t)Dd * Dd];

__device__ __forceinline__ uint32_t f2tf(float f)
{
    uint32_t u;
    asm("cvt.rna.tf32.f32 %0, %1;" : "=r"(u) : "f"(f));
    return u;
}
__device__ __forceinline__ float rndf(float f) { return __uint_as_float(f2tf(f)); }

__device__ __forceinline__ void cp16(uint32_t saddr, const void* gaddr)
{
    asm volatile("cp.async.cg.shared.global [%0], [%1], 16;" :: "r"(saddr), "l"(gaddr));
}
#define CP_COMMIT() asm volatile("cp.async.commit_group;")
#define CP_WAIT1()  asm volatile("cp.async.wait_group 1;")
#define CP_WAIT0()  asm volatile("cp.async.wait_group 0;")

// ---------------------------------------------------------------------------
// 128x128 tf32 MMA tile, cp.async double-buffered.
// 256 threads = 8 warps in 2(m) x 4(n); warp tile 64x32 = 4x4 m16n8k8 frags.
// Inputs MUST already be tf32-rounded fp32 bit patterns.
// acc[mi][nj][e]: e -> {(r,c),(r,c+1),(r+8,c),(r+8,c+1)},
//   r = lane>>2, c = (lane&3)*2 inside fragment (mi*16, nj*8).
// ---------------------------------------------------------------------------
template <bool BNK>
__device__ __forceinline__ void mma_tile128(
    const float* __restrict__ A, int lda,
    const float* __restrict__ Bm, int ldb,
    int kCount, float acc[4][4][4])
{
    extern __shared__ float sm[];
    float* As = sm;                       // [2][128][36]
    float* Bs = sm + 2 * STAGE_F;         // [2][ BNK ? 128*36 : 32*136 ]
    const int tid = threadIdx.x;
    const int lane = tid & 31, warp = tid >> 5;
    const int am = (warp >> 2) * 64, bn = (warp & 3) * 32;
    const int ar = lane >> 2, ac = lane & 3;

    auto load_stage = [&](int st, int k0) {
        float* Ad = As + st * STAGE_F;
        #pragma unroll
        for (int l = 0; l < 4; l++) {
            int c = tid + l * 256;
            int m = c >> 3, seg = (c & 7) << 2;
            cp16((uint32_t)__cvta_generic_to_shared(Ad + m * A_STRIDE + seg),
                 A + (size_t)m * lda + k0 + seg);
        }
        float* Bd = Bs + st * STAGE_F;
        if (BNK) {
            #pragma unroll
            for (int l = 0; l < 4; l++) {
                int c = tid + l * 256;
                int n = c >> 3, seg = (c & 7) << 2;
                cp16((uint32_t)__cvta_generic_to_shared(Bd + n * A_STRIDE + seg),
                     Bm + (size_t)n * ldb + k0 + seg);
            }
        } else {
            #pragma unroll
            for (int l = 0; l < 4; l++) {
                int c = tid + l * 256;
                int k = c >> 5, nseg = (c & 31) << 2;
                cp16((uint32_t)__cvta_generic_to_shared(Bd + k * B_STRIDE_KN + nseg),
                     Bm + (size_t)(k0 + k) * ldb + nseg);
            }
        }
    };

    const int nT = kCount >> 5;
    load_stage(0, 0);
    CP_COMMIT();

    for (int t = 0; t < nT; t++) {
        const int st = t & 1;
        if (t + 1 < nT) {
            load_stage(st ^ 1, (t + 1) * BKT);
            CP_COMMIT();
            CP_WAIT1();
        } else {
            CP_WAIT0();
        }
        __syncthreads();

        const float* Ast = As + st * STAGE_F;
        const float* Bst = Bs + st * STAGE_F;
        #pragma unroll
        for (int kg = 0; kg < 4; kg++) {
            const int kk = kg * 8;
            uint32_t a[4][4], b[4][2];
            #pragma unroll
            for (int mi = 0; mi < 4; mi++) {
                int mb = am + mi * 16 + ar;
                a[mi][0] = __float_as_uint(Ast[(size_t)mb * A_STRIDE + kk + ac]);
                a[mi][1] = __float_as_uint(Ast[(size_t)(mb + 8) * A_STRIDE + kk + ac]);
                a[mi][2] = __float_as_uint(Ast[(size_t)mb * A_STRIDE + kk + ac + 4]);
                a[mi][3] = __float_as_uint(Ast[(size_t)(mb + 8) * A_STRIDE + kk + ac + 4]);
            }
            #pragma unroll
            for (int nj = 0; nj < 4; nj++) {
                int nb = bn + nj * 8 + ar;
                if (BNK) {
                    b[nj][0] = __float_as_uint(Bst[(size_t)nb * A_STRIDE + kk + ac]);
                    b[nj][1] = __float_as_uint(Bst[(size_t)nb * A_STRIDE + kk + ac + 4]);
                } else {
                    b[nj][0] = __float_as_uint(Bst[(size_t)(kk + ac) * B_STRIDE_KN + nb]);
                    b[nj][1] = __float_as_uint(Bst[(size_t)(kk + ac + 4) * B_STRIDE_KN + nb]);
                }
            }
            #pragma unroll
            for (int mi = 0; mi < 4; mi++)
                #pragma unroll
                for (int nj = 0; nj < 4; nj++)
                    asm volatile(
                        "mma.sync.aligned.m16n8k8.row.col.f32.tf32.tf32.f32 "
                        "{%0,%1,%2,%3}, {%4,%5,%6,%7}, {%8,%9}, {%0,%1,%2,%3};"
                        : "+f"(acc[mi][nj][0]), "+f"(acc[mi][nj][1]),
                          "+f"(acc[mi][nj][2]), "+f"(acc[mi][nj][3])
                        : "r"(a[mi][0]), "r"(a[mi][1]), "r"(a[mi][2]), "r"(a[mi][3]),
                          "r"(b[nj][0]), "r"(b[nj][1]));
        }
        __syncthreads();
    }
}

// Epilogue index helpers
#define EPI_SETUP \
    const int lane = threadIdx.x & 31, warp = threadIdx.x >> 5; \
    const int am = (warp >> 2) * 64, bn = (warp & 3) * 32; \
    const int er = lane >> 2, ec = (lane & 3) * 2;

// ---------------------------------------------------------------------------
// LN helpers
// ---------------------------------------------------------------------------
__device__ __forceinline__ void block_sum2(float& s, float& q)
{
    __shared__ float shs[8], shq[8];
    __syncthreads();
    #pragma unroll
    for (int o = 16; o > 0; o >>= 1) {
        s += __shfl_xor_sync(0xffffffffu, s, o);
        q += __shfl_xor_sync(0xffffffffu, q, o);
    }
    int w = threadIdx.x >> 5;
    if ((threadIdx.x & 31) == 0) { shs[w] = s; shq[w] = q; }
    __syncthreads();
    s = 0.f; q = 0.f;
    #pragma unroll
    for (int i = 0; i < 8; i++) { s += shs[i]; q += shq[i]; }
}

__device__ __forceinline__ void ln512_pair(float v0, float v1, float& o0, float& o1)
{
    float s = v0 + v1, q = v0 * v0 + v1 * v1;
    block_sum2(s, q);
    float mu  = s * (1.f / 512.f);
    float var = q * (1.f / 512.f) - mu * mu;
    float r   = rsqrtf(var + LN_EPS);
    o0 = (v0 - mu) * r;
    o1 = (v1 - mu) * r;
}

// ---------------------------------------------------------------------------
// Pre-round pass (tf32 rounding of read-only inputs)
// ---------------------------------------------------------------------------
__global__ __launch_bounds__(256) void k_round(const float* __restrict__ src,
                                               float* __restrict__ dst, int n)
{
    for (int i = blockIdx.x * 256 + threadIdx.x; i < n; i += gridDim.x * 256)
        dst[i] = rndf(src[i]);
}

// ---------------------------------------------------------------------------
// Kernels
// ---------------------------------------------------------------------------

__global__ __launch_bounds__(256, 2) void k_inproj(const float* __restrict__ bias)
{
    int n0 = blockIdx.x * BNT, m0 = blockIdx.y * BMT;
    float acc[4][4][4] = {};
    mma_tile128<false>(g_x_r + (size_t)m0 * Dd, Dd, g_win_r + n0, Dd, Dd, acc);
    EPI_SETUP;
    #pragma unroll
    for (int mi = 0; mi < 4; mi++)
        #pragma unroll
        for (int nj = 0; nj < 4; nj++) {
            int m = m0 + am + mi * 16 + er;
            int n = n0 + bn + nj * 8 + ec;
            g_tmp[(size_t)m * Dd + n]           = acc[mi][nj][0] + bias[n];
            g_tmp[(size_t)m * Dd + n + 1]       = acc[mi][nj][1] + bias[n + 1];
            g_tmp[(size_t)(m + 8) * Dd + n]     = acc[mi][nj][2] + bias[n];
            g_tmp[(size_t)(m + 8) * Dd + n + 1] = acc[mi][nj][3] + bias[n + 1];
        }
}

__global__ __launch_bounds__(256) void k_ln_inproj()
{
    size_t row = blockIdx.x;
    const float* p = g_tmp + row * 512;
    int t = threadIdx.x;
    float o0, o1;
    ln512_pair(p[t], p[t + 256], o0, o1);
    g_xs[row * 512 + t] = o0;
    g_xs[row * 512 + t + 256] = o1;
    g_xs_r[row * 512 + t] = rndf(o0);
    g_xs_r[row * 512 + t + 256] = rndf(o1);
}

// encode + relu + rope. ec even -> rope pairs.
__global__ __launch_bounds__(256, 2) void k_enc_rope()
{
    int z = blockIdx.z;
    int b = z / NHh, h = z % NHh;
    int n0 = blockIdx.x * BNT, m0 = blockIdx.y * BMT;
    const float* A  = g_xs_r + (size_t)b * Tt * Dd + (size_t)m0 * Dd;
    const float* Bm = g_enc_r + (size_t)h * Dd * Nn + n0;
    float acc[4][4][4] = {};
    mma_tile128<false>(A, Dd, Bm, Nn, Dd, acc);
    EPI_SETUP;
    #pragma unroll
    for (int mi = 0; mi < 4; mi++)
        #pragma unroll
        for (int nj = 0; nj < 4; nj++) {
            int ne = n0 + bn + nj * 8 + ec;
            float freq = exp2f((float)ne * (-1.f / 16.f)) * (1.f / TWO_PI);
            #pragma unroll
            for (int hh = 0; hh < 2; hh++) {
                int t = m0 + am + mi * 16 + er + hh * 8;
                float v0 = fmaxf(acc[mi][nj][hh * 2], 0.f);
                float v1 = fmaxf(acc[mi][nj][hh * 2 + 1], 0.f);
                float ph = (float)t * freq;
                ph = (ph - floorf(ph)) * TWO_PI;
                float sp, cp;
                sincosf(ph, &sp, &cp);
                size_t base = ((size_t)z * Tt + t) * Nn + ne;
                g_xsp[base]     = v0;
                g_xsp[base + 1] = v1;
                g_qr[base]      = rndf(v0 * cp - v1 * sp);
                g_qr[base + 1]  = rndf(v1 * cp + v0 * sp);
            }
        }
}

// scores = QR @ QR^T, strict-lower causal; rounded at write.
__global__ __launch_bounds__(256, 2) void k_qk()
{
    int stile = blockIdx.x, ttile = blockIdx.y, z = blockIdx.z;
    if (stile > ttile) return;
    const float* Q  = g_qr + ((size_t)z * Tt + (size_t)ttile * BMT) * Nn;
    const float* Kp = g_qr + ((size_t)z * Tt + (size_t)stile * BNT) * Nn;
    float acc[4][4][4] = {};
    mma_tile128<true>(Q, Nn, Kp, Nn, Nn, acc);
    EPI_SETUP;
    #pragma unroll
    for (int mi = 0; mi < 4; mi++)
        #pragma unroll
        for (int nj = 0; nj < 4; nj++) {
            int t = ttile * BMT + am + mi * 16 + er;
            int s = stile * BNT + bn + nj * 8 + ec;
            size_t r0 = ((size_t)z * Tt + t) * Tt;
            size_t r1 = ((size_t)z * Tt + t + 8) * Tt;
            g_scores[r0 + s]     = (t > s)     ? rndf(acc[mi][nj][0]) : 0.f;
            g_scores[r0 + s + 1] = (t > s + 1) ? rndf(acc[mi][nj][1]) : 0.f;
            g_scores[r1 + s]     = (t + 8 > s)     ? rndf(acc[mi][nj][2]) : 0.f;
            g_scores[r1 + s + 1] = (t + 8 > s + 1) ? rndf(acc[mi][nj][3]) : 0.f;
        }
}

// yKV = scores @ xs (causal K-extent)
__global__ __launch_bounds__(256, 2) void k_sv()
{
    int dtile = blockIdx.x, ttile = blockIdx.y, z = blockIdx.z;
    int b = z / NHh;
    const float* A  = g_scores + ((size_t)z * Tt + (size_t)ttile * BMT) * Tt;
    const float* Bm = g_xs_r + (size_t)b * Tt * Dd + dtile * BNT;
    float acc[4][4][4] = {};
    mma_tile128<false>(A, Tt, Bm, Dd, (ttile + 1) * BMT, acc);
    EPI_SETUP;
    #pragma unroll
    for (int mi = 0; mi < 4; mi++)
        #pragma unroll
        for (int nj = 0; nj < 4; nj++) {
            int t = ttile * BMT + am + mi * 16 + er;
            int d = dtile * BNT + bn + nj * 8 + ec;
            size_t r0 = ((size_t)z * Tt + t) * Dd;
            size_t r1 = ((size_t)z * Tt + t + 8) * Dd;
            g_ykv[r0 + d]     = acc[mi][nj][0];
            g_ykv[r0 + d + 1] = acc[mi][nj][1];
            g_ykv[r1 + d]     = acc[mi][nj][2];
            g_ykv[r1 + d + 1] = acc[mi][nj][3];
        }
}

// LN of yKV, rounded at write (feeds GEMM A only).
__global__ __launch_bounds__(256) void k_ln_ykv()
{
    size_t row = blockIdx.x;
    float* p = g_ykv + row * 512;
    int t = threadIdx.x;
    float o0, o1;
    ln512_pair(p[t], p[t + 256], o0, o1);
    p[t] = rndf(o0);
    p[t + 256] = rndf(o1);
}

// y_sparse = relu(ln(yKV) @ encv[h]); xy = x_sparse * y_sparse -> [b,t,h,n], rounded.
__global__ __launch_bounds__(256, 2) void k_venc_mul()
{
    int z = blockIdx.z;
    int b = z / NHh, h = z % NHh;
    int n0 = blockIdx.x * BNT, m0 = blockIdx.y * BMT;
    const float* A  = g_ykv + (size_t)z * Tt * Dd + (size_t)m0 * Dd;
    const float* Bm = g_encv_r + (size_t)h * Dd * Nn + n0;
    float acc[4][4][4] = {};
    mma_tile128<false>(A, Dd, Bm, Nn, Dd, acc);
    EPI_SETUP;
    #pragma unroll
    for (int mi = 0; mi < 4; mi++)
        #pragma unroll
        for (int nj = 0; nj < 4; nj++) {
            int n = n0 + bn + nj * 8 + ec;
            #pragma unroll
            for (int hh = 0; hh < 2; hh++) {
                int t = m0 + am + mi * 16 + er + hh * 8;
                size_t src = ((size_t)z * Tt + t) * Nn + n;
                size_t dst = (((size_t)(b * Tt + t)) * NHh + h) * Nn + n;
                float y0 = fmaxf(acc[mi][nj][hh * 2], 0.f);
                float y1 = fmaxf(acc[mi][nj][hh * 2 + 1], 0.f);
                g_xy[dst]     = rndf(y0 * g_xsp[src]);
                g_xy[dst + 1] = rndf(y1 * g_xsp[src + 1]);
            }
        }
}

// yMLP = xy[4096,2048] @ decoder[2048,512] -> g_tmp (full precision out)
__global__ __launch_bounds__(256, 2) void k_dec()
{
    int n0 = blockIdx.x * BNT, m0 = blockIdx.y * BMT;
    float acc[4][4][4] = {};
    mma_tile128<false>(g_xy + (size_t)m0 * HN, HN, g_dec_r + n0, Dd, HN, acc);
    EPI_SETUP;
    #pragma unroll
    for (int mi = 0; mi < 4; mi++)
        #pragma unroll
        for (int nj = 0; nj < 4; nj++) {
            int m = m0 + am + mi * 16 + er;
            int n = n0 + bn + nj * 8 + ec;
            g_tmp[(size_t)m * Dd + n]           = acc[mi][nj][0];
            g_tmp[(size_t)m * Dd + n + 1]       = acc[mi][nj][1];
            g_tmp[(size_t)(m + 8) * Dd + n]     = acc[mi][nj][2];
            g_tmp[(size_t)(m + 8) * Dd + n + 1] = acc[mi][nj][3];
        }
}

__global__ __launch_bounds__(256) void k_resid_ln()
{
    size_t row = blockIdx.x;
    const float* a = g_xs + row * 512;
    const float* bp = g_tmp + row * 512;
    int t = threadIdx.x;
    float l0, l1;
    ln512_pair(bp[t], bp[t + 256], l0, l1);
    float t0 = a[t] + l0, t1 = a[t + 256] + l1;
    float o0, o1;
    ln512_pair(t0, t1, o0, o1);
    g_xs[row * 512 + t] = o0;
    g_xs[row * 512 + t + 256] = o1;
    g_xs_r[row * 512 + t] = rndf(o0);
    g_xs_r[row * 512 + t + 256] = rndf(o1);
}

__global__ __launch_bounds__(256, 2) void k_head(
    const float* __restrict__ hb, float* __restrict__ out)
{
    int n0 = blockIdx.x * BNT, m0 = blockIdx.y * BMT;
    float acc[4][4][4] = {};
    mma_tile128<false>(g_xs_r + (size_t)m0 * Dd, Dd, g_hw_r + n0, Dd, Dd, acc);
    EPI_SETUP;
    #pragma unroll
    for (int mi = 0; mi < 4; mi++)
        #pragma unroll
        for (int nj = 0; nj < 4; nj++) {
            int m = m0 + am + mi * 16 + er;
            int n = n0 + bn + nj * 8 + ec;
            out[(size_t)m * Dd + n]           = acc[mi][nj][0] + hb[n];
            out[(size_t)m * Dd + n + 1]       = acc[mi][nj][1] + hb[n + 1];
            out[(size_t)(m + 8) * Dd + n]     = acc[mi][nj][2] + hb[n];
            out[(size_t)(m + 8) * Dd + n + 1] = acc[mi][nj][3] + hb[n + 1];
        }
}

// ---------------------------------------------------------------------------
extern "C" void kernel_launch(void* const* d_in, const int* in_sizes, int n_in,
                              void* d_out, int out_size)
{
    const float* x    = (const float*)d_in[0];
    const float* w_in = (const float*)d_in[1];
    const float* b_in = (const float*)d_in[2];
    const float* enc  = (const float*)d_in[3];
    const float* encv = (const float*)d_in[4];
    const float* dec  = (const float*)d_in[5];
    const float* hw   = (const float*)d_in[6];
    const float* hb   = (const float*)d_in[7];
    float* out = (float*)d_out;

    // Opt in to >48KB dynamic smem for GEMM kernels (host-side attr, capture-safe).
    static bool attr_done = false;
    if (!attr_done) {
        cudaFuncSetAttribute(k_inproj,   cudaFuncAttributeMaxDynamicSharedMemorySize, SMEM_BYTES);
        cudaFuncSetAttribute(k_enc_rope, cudaFuncAttributeMaxDynamicSharedMemorySize, SMEM_BYTES);
        cudaFuncSetAttribute(k_qk,       cudaFuncAttributeMaxDynamicSharedMemorySize, SMEM_BYTES);
        cudaFuncSetAttribute(k_sv,       cudaFuncAttributeMaxDynamicSharedMemorySize, SMEM_BYTES);
        cudaFuncSetAttribute(k_venc_mul, cudaFuncAttributeMaxDynamicSharedMemorySize, SMEM_BYTES);
        cudaFuncSetAttribute(k_dec,      cudaFuncAttributeMaxDynamicSharedMemorySize, SMEM_BYTES);
        cudaFuncSetAttribute(k_head,     cudaFuncAttributeMaxDynamicSharedMemorySize, SMEM_BYTES);
        attr_done = true;
    }

    dim3 blk(256);

    // Pre-round all GEMM-consumed inputs to tf32 bit patterns.
    float* xr; cudaGetSymbolAddress((void**)&xr, g_x_r);
    float* wr; cudaGetSymbolAddress((void**)&wr, g_win_r);
    float* er; cudaGetSymbolAddress((void**)&er, g_enc_r);
    float* evr; cudaGetSymbolAddress((void**)&evr, g_encv_r);
    float* dr; cudaGetSymbolAddress((void**)&dr, g_dec_r);
    float* hr; cudaGetSymbolAddress((void**)&hr, g_hw_r);
    k_round<<<512, 256>>>(x, xr, Bb * Tt * Dd);
    k_round<<<256, 256>>>(w_in, wr, Dd * Dd);
    k_round<<<512, 256>>>(enc, er, NHh * Dd * Nn);
    k_round<<<512, 256>>>(encv, evr, NHh * Dd * Nn);
    k_round<<<512, 256>>>(dec, dr, HN * Dd);
    k_round<<<256, 256>>>(hw, hr, Dd * Dd);

    k_inproj<<<dim3(Dd / BNT, BT / BMT), blk, SMEM_BYTES>>>(b_in);
    k_ln_inproj<<<BT, 256>>>();

    for (int layer = 0; layer < 3; layer++) {
        k_enc_rope<<<dim3(Nn / BNT, Tt / BMT, BH), blk, SMEM_BYTES>>>();
        k_qk<<<dim3(Tt / BNT, Tt / BMT, BH), blk, SMEM_BYTES>>>();
        k_sv<<<dim3(Dd / BNT, Tt / BMT, BH), blk, SMEM_BYTES>>>();
        k_ln_ykv<<<BH * Tt, 256>>>();
        k_venc_mul<<<dim3(Nn / BNT, Tt / BMT, BH), blk, SMEM_BYTES>>>();
        k_dec<<<dim3(Dd / BNT, BT / BMT), blk, SMEM_BYTES>>>();
        k_resid_ln<<<BT, 256>>>();
    }

    k_head<<<dim3(Dd / BNT, BT / BMT), blk, SMEM_BYTES>>>(hb, out);
}

// round 7
// speedup vs baseline: 2.9707x; 1.0122x over previous
#include <cuda_runtime.h>
#include <math.h>
#include <stdint.h>

// ---------------------------------------------------------------------------
// BDH block: B=2, T=2048, D=512, NH=8, N=256, 3 layers.
// tf32 mma.sync m16n8k8, fp32 accumulate.
// cp.async double-buffered tiles; ldmatrix fragment loads; pre-rounded inputs.
// ---------------------------------------------------------------------------

constexpr int Bb = 2, Tt = 2048, Dd = 512, NHh = 8, Nn = 256;
constexpr int BT = Bb * Tt;        // 4096
constexpr int BH = Bb * NHh;       // 16
constexpr int HN = NHh * Nn;       // 2048
constexpr float LN_EPS = 1e-5f;
constexpr float TWO_PI = 6.283185307179586f;

#define BMT 128
#define BNT 128
#define BKT 32

constexpr int A_STRIDE = 36;                 // floats per A row (banks 4r mod 32 distinct)
constexpr int B_STRIDE_KN = 136;             // floats per B[k][n] row
constexpr int STAGE_F = 128 * 36;            // 4608 floats per stage
constexpr int SMEM_BYTES = 4 * STAGE_F * 4;  // 2 stages A + 2 stages B = 73728 B

// Scratch (device globals: no allocation allowed)
__device__ float g_xs   [(size_t)Bb * Tt * Dd];           // full-precision residual stream
__device__ float g_xs_r [(size_t)Bb * Tt * Dd];           // tf32-rounded copy for GEMMs
__device__ float g_tmp  [(size_t)Bb * Tt * Dd];
__device__ float g_xsp  [(size_t)BH * Tt * Nn];           // full precision (gating only)
__device__ float g_qr   [(size_t)BH * Tt * Nn];           // rounded at write
__device__ float g_ykv  [(size_t)BH * Tt * Dd];           // LN writes rounded
__device__ float g_xy   [(size_t)Bb * Tt * NHh * Nn];     // rounded at write
__device__ float g_scores[(size_t)BH * Tt * Tt];          // rounded at write
// Pre-rounded inputs
__device__ float g_x_r  [(size_t)Bb * Tt * Dd];
__device__ float g_win_r[(size_t)Dd * Dd];
__device__ float g_enc_r[(size_t)NHh * Dd * Nn];
__device__ float g_encv_r[(size_t)NHh * Dd * Nn];
__device__ float g_dec_r[(size_t)HN * Dd];
__device__ float g_hw_r [(size_t)Dd * Dd];

__device__ __forceinline__ uint32_t f2tf(float f)
{
    uint32_t u;
    asm("cvt.rna.tf32.f32 %0, %1;" : "=r"(u) : "f"(f));
    return u;
}
__device__ __forceinline__ float rndf(float f) { return __uint_as_float(f2tf(f)); }

__device__ __forceinline__ void cp16(uint32_t saddr, const void* gaddr)
{
    asm volatile("cp.async.cg.shared.global [%0], [%1], 16;" :: "r"(saddr), "l"(gaddr));
}
#define CP_COMMIT() asm volatile("cp.async.commit_group;")
#define CP_WAIT1()  asm volatile("cp.async.wait_group 1;")
#define CP_WAIT0()  asm volatile("cp.async.wait_group 0;")

__device__ __forceinline__ void ldsm_x4(uint32_t* r, uint32_t addr)
{
    asm volatile("ldmatrix.sync.aligned.m8n8.x4.shared.b16 {%0,%1,%2,%3}, [%4];"
                 : "=r"(r[0]), "=r"(r[1]), "=r"(r[2]), "=r"(r[3]) : "r"(addr));
}

// ---------------------------------------------------------------------------
// 128x128 tf32 MMA tile, cp.async double-buffered, ldmatrix fragment loads.
// 256 threads = 8 warps in 2(m) x 4(n); warp tile 64x32 = 4x4 m16n8k8 frags.
// Inputs MUST already be tf32-rounded fp32 bit patterns.
//
// A fragment (mi, kg): four 8rows x 16B matrices at
//   row = am + mi*16 + (lane&7) + 8*((lane>>3)&1), colf = kk + 4*(lane>>4)
// -> one ldmatrix.x4 yields {a0,a1,a2,a3} in mma order.
// B fragment (BNK=true): row n = bn + g*16 + (lane&7) + 8*(lane>>4),
//   colf = kk + 4*((lane>>3)&1) -> x4 yields {b[2g][0],b[2g][1],b[2g+1][0],b[2g+1][1]}.
// acc[mi][nj][e]: e -> {(r,c),(r,c+1),(r+8,c),(r+8,c+1)},
//   r = lane>>2, c = (lane&3)*2 inside fragment (mi*16, nj*8).
// ---------------------------------------------------------------------------
template <bool BNK>
__device__ __forceinline__ void mma_tile128(
    const float* __restrict__ A, int lda,
    const float* __restrict__ Bm, int ldb,
    int kCount, float acc[4][4][4])
{
    extern __shared__ float sm[];
    float* As = sm;                       // [2][128][36]
    float* Bs = sm + 2 * STAGE_F;         // [2][...]
    const int tid = threadIdx.x;
    const int lane = tid & 31, warp = tid >> 5;
    const int am = (warp >> 2) * 64, bn = (warp & 3) * 32;
    const int ar = lane >> 2, ac = lane & 3;
    // ldmatrix lane->row/col offsets
    const int lrowA = (lane & 7) + 8 * ((lane >> 3) & 1);
    const int lcolA = (lane >> 4) * 4;
    const int lrowB = (lane & 7) + 8 * (lane >> 4);
    const int lcolB = ((lane >> 3) & 1) * 4;

    const uint32_t sA0 = (uint32_t)__cvta_generic_to_shared(As);
    const uint32_t sB0 = (uint32_t)__cvta_generic_to_shared(Bs);

    auto load_stage = [&](int st, int k0) {
        float* Ad = As + st * STAGE_F;
        #pragma unroll
        for (int l = 0; l < 4; l++) {
            int c = tid + l * 256;
            int m = c >> 3, seg = (c & 7) << 2;
            cp16((uint32_t)__cvta_generic_to_shared(Ad + m * A_STRIDE + seg),
                 A + (size_t)m * lda + k0 + seg);
        }
        float* Bd = Bs + st * STAGE_F;
        if (BNK) {
            #pragma unroll
            for (int l = 0; l < 4; l++) {
                int c = tid + l * 256;
                int n = c >> 3, seg = (c & 7) << 2;
                cp16((uint32_t)__cvta_generic_to_shared(Bd + n * A_STRIDE + seg),
                     Bm + (size_t)n * ldb + k0 + seg);
            }
        } else {
            #pragma unroll
            for (int l = 0; l < 4; l++) {
                int c = tid + l * 256;
                int k = c >> 5, nseg = (c & 31) << 2;
                cp16((uint32_t)__cvta_generic_to_shared(Bd + k * B_STRIDE_KN + nseg),
                     Bm + (size_t)(k0 + k) * ldb + nseg);
            }
        }
    };

    const int nT = kCount >> 5;
    load_stage(0, 0);
    CP_COMMIT();

    for (int t = 0; t < nT; t++) {
        const int st = t & 1;
        if (t + 1 < nT) {
            load_stage(st ^ 1, (t + 1) * BKT);
            CP_COMMIT();
            CP_WAIT1();
        } else {
            CP_WAIT0();
        }
        __syncthreads();

        const uint32_t aS = sA0 + st * (STAGE_F * 4);
        const uint32_t bS = sB0 + st * (STAGE_F * 4);
        const float* Bst = Bs + st * STAGE_F;
        #pragma unroll
        for (int kg = 0; kg < 4; kg++) {
            const int kk = kg * 8;
            uint32_t a[4][4], b[4][2];
            #pragma unroll
            for (int mi = 0; mi < 4; mi++)
                ldsm_x4(a[mi],
                        aS + (uint32_t)(((am + mi * 16 + lrowA) * A_STRIDE + kk + lcolA) * 4));
            if (BNK) {
                ldsm_x4(&b[0][0],
                        bS + (uint32_t)(((bn + lrowB) * A_STRIDE + kk + lcolB) * 4));
                ldsm_x4(&b[2][0],
                        bS + (uint32_t)(((bn + 16 + lrowB) * A_STRIDE + kk + lcolB) * 4));
            } else {
                #pragma unroll
                for (int nj = 0; nj < 4; nj++) {
                    int nb = bn + nj * 8 + ar;
                    b[nj][0] = __float_as_uint(Bst[(size_t)(kk + ac) * B_STRIDE_KN + nb]);
                    b[nj][1] = __float_as_uint(Bst[(size_t)(kk + ac + 4) * B_STRIDE_KN + nb]);
                }
            }
            #pragma unroll
            for (int mi = 0; mi < 4; mi++)
                #pragma unroll
                for (int nj = 0; nj < 4; nj++)
                    asm volatile(
                        "mma.sync.aligned.m16n8k8.row.col.f32.tf32.tf32.f32 "
                        "{%0,%1,%2,%3}, {%4,%5,%6,%7}, {%8,%9}, {%0,%1,%2,%3};"
                        : "+f"(acc[mi][nj][0]), "+f"(acc[mi][nj][1]),
                          "+f"(acc[mi][nj][2]), "+f"(acc[mi][nj][3])
                        : "r"(a[mi][0]), "r"(a[mi][1]), "r"(a[mi][2]), "r"(a[mi][3]),
                          "r"(b[nj][0]), "r"(b[nj][1]));
        }
        __syncthreads();
    }
}

// Epilogue index helpers
#define EPI_SETUP \
    const int lane = threadIdx.x & 31, warp = threadIdx.x >> 5; \
    const int am = (warp >> 2) * 64, bn = (warp & 3) * 32; \
    const int er = lane >> 2, ec = (lane & 3) * 2;

// ---------------------------------------------------------------------------
// LN helpers
// ---------------------------------------------------------------------------
__device__ __forceinline__ void block_sum2(float& s, float& q)
{
    __shared__ float shs[8], shq[8];
    __syncthreads();
    #pragma unroll
    for (int o = 16; o > 0; o >>= 1) {
        s += __shfl_xor_sync(0xffffffffu, s, o);
        q += __shfl_xor_sync(0xffffffffu, q, o);
    }
    int w = threadIdx.x >> 5;
    if ((threadIdx.x & 31) == 0) { shs[w] = s; shq[w] = q; }
    __syncthreads();
    s = 0.f; q = 0.f;
    #pragma unroll
    for (int i = 0; i < 8; i++) { s += shs[i]; q += shq[i]; }
}

__device__ __forceinline__ void ln512_pair(float v0, float v1, float& o0, float& o1)
{
    float s = v0 + v1, q = v0 * v0 + v1 * v1;
    block_sum2(s, q);
    float mu  = s * (1.f / 512.f);
    float var = q * (1.f / 512.f) - mu * mu;
    float r   = rsqrtf(var + LN_EPS);
    o0 = (v0 - mu) * r;
    o1 = (v1 - mu) * r;
}

// ---------------------------------------------------------------------------
// Pre-round pass (tf32 rounding of read-only inputs)
// ---------------------------------------------------------------------------
__global__ __launch_bounds__(256) void k_round(const float* __restrict__ src,
                                               float* __restrict__ dst, int n)
{
    for (int i = blockIdx.x * 256 + threadIdx.x; i < n; i += gridDim.x * 256)
        dst[i] = rndf(src[i]);
}

// ---------------------------------------------------------------------------
// Kernels
// ---------------------------------------------------------------------------

__global__ __launch_bounds__(256, 2) void k_inproj(const float* __restrict__ bias)
{
    int n0 = blockIdx.x * BNT, m0 = blockIdx.y * BMT;
    float acc[4][4][4] = {};
    mma_tile128<false>(g_x_r + (size_t)m0 * Dd, Dd, g_win_r + n0, Dd, Dd, acc);
    EPI_SETUP;
    #pragma unroll
    for (int mi = 0; mi < 4; mi++)
        #pragma unroll
        for (int nj = 0; nj < 4; nj++) {
            int m = m0 + am + mi * 16 + er;
            int n = n0 + bn + nj * 8 + ec;
            g_tmp[(size_t)m * Dd + n]           = acc[mi][nj][0] + bias[n];
            g_tmp[(size_t)m * Dd + n + 1]       = acc[mi][nj][1] + bias[n + 1];
            g_tmp[(size_t)(m + 8) * Dd + n]     = acc[mi][nj][2] + bias[n];
            g_tmp[(size_t)(m + 8) * Dd + n + 1] = acc[mi][nj][3] + bias[n + 1];
        }
}

__global__ __launch_bounds__(256) void k_ln_inproj()
{
    size_t row = blockIdx.x;
    const float* p = g_tmp + row * 512;
    int t = threadIdx.x;
    float o0, o1;
    ln512_pair(p[t], p[t + 256], o0, o1);
    g_xs[row * 512 + t] = o0;
    g_xs[row * 512 + t + 256] = o1;
    g_xs_r[row * 512 + t] = rndf(o0);
    g_xs_r[row * 512 + t + 256] = rndf(o1);
}

// encode + relu + rope. ec even -> rope pairs.
__global__ __launch_bounds__(256, 2) void k_enc_rope()
{
    int z = blockIdx.z;
    int b = z / NHh, h = z % NHh;
    int n0 = blockIdx.x * BNT, m0 = blockIdx.y * BMT;
    const float* A  = g_xs_r + (size_t)b * Tt * Dd + (size_t)m0 * Dd;
    const float* Bm = g_enc_r + (size_t)h * Dd * Nn + n0;
    float acc[4][4][4] = {};
    mma_tile128<false>(A, Dd, Bm, Nn, Dd, acc);
    EPI_SETUP;
    #pragma unroll
    for (int mi = 0; mi < 4; mi++)
        #pragma unroll
        for (int nj = 0; nj < 4; nj++) {
            int ne = n0 + bn + nj * 8 + ec;
            float freq = exp2f((float)ne * (-1.f / 16.f)) * (1.f / TWO_PI);
            #pragma unroll
            for (int hh = 0; hh < 2; hh++) {
                int t = m0 + am + mi * 16 + er + hh * 8;
                float v0 = fmaxf(acc[mi][nj][hh * 2], 0.f);
                float v1 = fmaxf(acc[mi][nj][hh * 2 + 1], 0.f);
                float ph = (float)t * freq;
                ph = (ph - floorf(ph)) * TWO_PI;
                float sp, cp;
                sincosf(ph, &sp, &cp);
                size_t base = ((size_t)z * Tt + t) * Nn + ne;
                g_xsp[base]     = v0;
                g_xsp[base + 1] = v1;
                g_qr[base]      = rndf(v0 * cp - v1 * sp);
                g_qr[base + 1]  = rndf(v1 * cp + v0 * sp);
            }
        }
}

// scores = QR @ QR^T, strict-lower causal; rounded at write.
__global__ __launch_bounds__(256, 2) void k_qk()
{
    int stile = blockIdx.x, ttile = blockIdx.y, z = blockIdx.z;
    if (stile > ttile) return;
    const float* Q  = g_qr + ((size_t)z * Tt + (size_t)ttile * BMT) * Nn;
    const float* Kp = g_qr + ((size_t)z * Tt + (size_t)stile * BNT) * Nn;
    float acc[4][4][4] = {};
    mma_tile128<true>(Q, Nn, Kp, Nn, Nn, acc);
    EPI_SETUP;
    #pragma unroll
    for (int mi = 0; mi < 4; mi++)
        #pragma unroll
        for (int nj = 0; nj < 4; nj++) {
            int t = ttile * BMT + am + mi * 16 + er;
            int s = stile * BNT + bn + nj * 8 + ec;
            size_t r0 = ((size_t)z * Tt + t) * Tt;
            size_t r1 = ((size_t)z * Tt + t + 8) * Tt;
            g_scores[r0 + s]     = (t > s)     ? rndf(acc[mi][nj][0]) : 0.f;
            g_scores[r0 + s + 1] = (t > s + 1) ? rndf(acc[mi][nj][1]) : 0.f;
            g_scores[r1 + s]     = (t + 8 > s)     ? rndf(acc[mi][nj][2]) : 0.f;
            g_scores[r1 + s + 1] = (t + 8 > s + 1) ? rndf(acc[mi][nj][3]) : 0.f;
        }
}

// yKV = scores @ xs (causal K-extent)
__global__ __launch_bounds__(256, 2) void k_sv()
{
    int dtile = blockIdx.x, ttile = blockIdx.y, z = blockIdx.z;
    int b = z / NHh;
    const float* A  = g_scores + ((size_t)z * Tt + (size_t)ttile * BMT) * Tt;
    const float* Bm = g_xs_r + (size_t)b * Tt * Dd + dtile * BNT;
    float acc[4][4][4] = {};
    mma_tile128<false>(A, Tt, Bm, Dd, (ttile + 1) * BMT, acc);
    EPI_SETUP;
    #pragma unroll
    for (int mi = 0; mi < 4; mi++)
        #pragma unroll
        for (int nj = 0; nj < 4; nj++) {
            int t = ttile * BMT + am + mi * 16 + er;
            int d = dtile * BNT + bn + nj * 8 + ec;
            size_t r0 = ((size_t)z * Tt + t) * Dd;
            size_t r1 = ((size_t)z * Tt + t + 8) * Dd;
            g_ykv[r0 + d]     = acc[mi][nj][0];
            g_ykv[r0 + d + 1] = acc[mi][nj][1];
            g_ykv[r1 + d]     = acc[mi][nj][2];
            g_ykv[r1 + d + 1] = acc[mi][nj][3];
        }
}

// LN of yKV, rounded at write (feeds GEMM A only).
__global__ __launch_bounds__(256) void k_ln_ykv()
{
    size_t row = blockIdx.x;
    float* p = g_ykv + row * 512;
    int t = threadIdx.x;
    float o0, o1;
    ln512_pair(p[t], p[t + 256], o0, o1);
    p[t] = rndf(o0);
    p[t + 256] = rndf(o1);
}

// y_sparse = relu(ln(yKV) @ encv[h]); xy = x_sparse * y_sparse -> [b,t,h,n], rounded.
__global__ __launch_bounds__(256, 2) void k_venc_mul()
{
    int z = blockIdx.z;
    int b = z / NHh, h = z % NHh;
    int n0 = blockIdx.x * BNT, m0 = blockIdx.y * BMT;
    const float* A  = g_ykv + (size_t)z * Tt * Dd + (size_t)m0 * Dd;
    const float* Bm = g_encv_r + (size_t)h * Dd * Nn + n0;
    float acc[4][4][4] = {};
    mma_tile128<false>(A, Dd, Bm, Nn, Dd, acc);
    EPI_SETUP;
    #pragma unroll
    for (int mi = 0; mi < 4; mi++)
        #pragma unroll
        for (int nj = 0; nj < 4; nj++) {
            int n = n0 + bn + nj * 8 + ec;
            #pragma unroll
            for (int hh = 0; hh < 2; hh++) {
                int t = m0 + am + mi * 16 + er + hh * 8;
                size_t src = ((size_t)z * Tt + t) * Nn + n;
                size_t dst = (((size_t)(b * Tt + t)) * NHh + h) * Nn + n;
                float y0 = fmaxf(acc[mi][nj][hh * 2], 0.f);
                float y1 = fmaxf(acc[mi][nj][hh * 2 + 1], 0.f);
                g_xy[dst]     = rndf(y0 * g_xsp[src]);
                g_xy[dst + 1] = rndf(y1 * g_xsp[src + 1]);
            }
        }
}

// yMLP = xy[4096,2048] @ decoder[2048,512] -> g_tmp (full precision out)
__global__ __launch_bounds__(256, 2) void k_dec()
{
    int n0 = blockIdx.x * BNT, m0 = blockIdx.y * BMT;
    float acc[4][4][4] = {};
    mma_tile128<false>(g_xy + (size_t)m0 * HN, HN, g_dec_r + n0, Dd, HN, acc);
    EPI_SETUP;
    #pragma unroll
    for (int mi = 0; mi < 4; mi++)
        #pragma unroll
        for (int nj = 0; nj < 4; nj++) {
            int m = m0 + am + mi * 16 + er;
            int n = n0 + bn + nj * 8 + ec;
            g_tmp[(size_t)m * Dd + n]           = acc[mi][nj][0];
            g_tmp[(size_t)m * Dd + n + 1]       = acc[mi][nj][1];
            g_tmp[(size_t)(m + 8) * Dd + n]     = acc[mi][nj][2];
            g_tmp[(size_t)(m + 8) * Dd + n + 1] = acc[mi][nj][3];
        }
}

__global__ __launch_bounds__(256) void k_resid_ln()
{
    size_t row = blockIdx.x;
    const float* a = g_xs + row * 512;
    const float* bp = g_tmp + row * 512;
    int t = threadIdx.x;
    float l0, l1;
    ln512_pair(bp[t], bp[t + 256], l0, l1);
    float t0 = a[t] + l0, t1 = a[t + 256] + l1;
    float o0, o1;
    ln512_pair(t0, t1, o0, o1);
    g_xs[row * 512 + t] = o0;
    g_xs[row * 512 + t + 256] = o1;
    g_xs_r[row * 512 + t] = rndf(o0);
    g_xs_r[row * 512 + t + 256] = rndf(o1);
}

__global__ __launch_bounds__(256, 2) void k_head(
    const float* __restrict__ hb, float* __restrict__ out)
{
    int n0 = blockIdx.x * BNT, m0 = blockIdx.y * BMT;
    float acc[4][4][4] = {};
    mma_tile128<false>(g_xs_r + (size_t)m0 * Dd, Dd, g_hw_r + n0, Dd, Dd, acc);
    EPI_SETUP;
    #pragma unroll
    for (int mi = 0; mi < 4; mi++)
        #pragma unroll
        for (int nj = 0; nj < 4; nj++) {
            int m = m0 + am + mi * 16 + er;
            int n = n0 + bn + nj * 8 + ec;
            out[(size_t)m * Dd + n]           = acc[mi][nj][0] + hb[n];
            out[(size_t)m * Dd + n + 1]       = acc[mi][nj][1] + hb[n + 1];
            out[(size_t)(m + 8) * Dd + n]     = acc[mi][nj][2] + hb[n];
            out[(size_t)(m + 8) * Dd + n + 1] = acc[mi][nj][3] + hb[n + 1];
        }
}

// ---------------------------------------------------------------------------
extern "C" void kernel_launch(void* const* d_in, const int* in_sizes, int n_in,
                              void* d_out, int out_size)
{
    const float* x    = (const float*)d_in[0];
    const float* w_in = (const float*)d_in[1];
    const float* b_in = (const float*)d_in[2];
    const float* enc  = (const float*)d_in[3];
    const float* encv = (const float*)d_in[4];
    const float* dec  = (const float*)d_in[5];
    const float* hw   = (const float*)d_in[6];
    const float* hb   = (const float*)d_in[7];
    float* out = (float*)d_out;

    static bool attr_done = false;
    if (!attr_done) {
        cudaFuncSetAttribute(k_inproj,   cudaFuncAttributeMaxDynamicSharedMemorySize, SMEM_BYTES);
        cudaFuncSetAttribute(k_enc_rope, cudaFuncAttributeMaxDynamicSharedMemorySize, SMEM_BYTES);
        cudaFuncSetAttribute(k_qk,       cudaFuncAttributeMaxDynamicSharedMemorySize, SMEM_BYTES);
        cudaFuncSetAttribute(k_sv,       cudaFuncAttributeMaxDynamicSharedMemorySize, SMEM_BYTES);
        cudaFuncSetAttribute(k_venc_mul, cudaFuncAttributeMaxDynamicSharedMemorySize, SMEM_BYTES);
        cudaFuncSetAttribute(k_dec,      cudaFuncAttributeMaxDynamicSharedMemorySize, SMEM_BYTES);
        cudaFuncSetAttribute(k_head,     cudaFuncAttributeMaxDynamicSharedMemorySize, SMEM_BYTES);
        attr_done = true;
    }

    dim3 blk(256);

    float* xr; cudaGetSymbolAddress((void**)&xr, g_x_r);
    float* wr; cudaGetSymbolAddress((void**)&wr, g_win_r);
    float* er; cudaGetSymbolAddress((void**)&er, g_enc_r);
    float* evr; cudaGetSymbolAddress((void**)&evr, g_encv_r);
    float* dr; cudaGetSymbolAddress((void**)&dr, g_dec_r);
    float* hr; cudaGetSymbolAddress((void**)&hr, g_hw_r);
    k_round<<<512, 256>>>(x, xr, Bb * Tt * Dd);
    k_round<<<256, 256>>>(w_in, wr, Dd * Dd);
    k_round<<<512, 256>>>(enc, er, NHh * Dd * Nn);
    k_round<<<512, 256>>>(encv, evr, NHh * Dd * Nn);
    k_round<<<512, 256>>>(dec, dr, HN * Dd);
    k_round<<<256, 256>>>(hw, hr, Dd * Dd);

    k_inproj<<<dim3(Dd / BNT, BT / BMT), blk, SMEM_BYTES>>>(b_in);
    k_ln_inproj<<<BT, 256>>>();

    for (int layer = 0; layer < 3; layer++) {
        k_enc_rope<<<dim3(Nn / BNT, Tt / BMT, BH), blk, SMEM_BYTES>>>();
        k_qk<<<dim3(Tt / BNT, Tt / BMT, BH), blk, SMEM_BYTES>>>();
        k_sv<<<dim3(Dd / BNT, Tt / BMT, BH), blk, SMEM_BYTES>>>();
        k_ln_ykv<<<BH * Tt, 256>>>();
        k_venc_mul<<<dim3(Nn / BNT, Tt / BMT, BH), blk, SMEM_BYTES>>>();
        k_dec<<<dim3(Dd / BNT, BT / BMT), blk, SMEM_BYTES>>>();
        k_resid_ln<<<BT, 256>>>();
    }

    k_head<<<dim3(Dd / BNT, BT / BMT), blk, SMEM_BYTES>>>(hb, out);
}